// round 1
// baseline (speedup 1.0000x reference)
#include <cuda_runtime.h>
#include <mma.h>
#include <math.h>

using namespace nvcuda;

#define SB   128      // batch (graphs)
#define NN   512      // nodes per graph
#define PF   92       // node feature dim
#define K0   604      // PF + NN
#define DD   128      // hidden dim of GCN layers
#define HID  256
#define MAXD 96
#define ROWS (SB*NN)  // 65536

// ---------------- scratch (static device globals; no allocations) -----------
__device__ float g_dinv[ROWS];
__device__ int   g_cnt[ROWS];
__device__ int   g_nbr[(size_t)ROWS*MAXD];
__device__ float g_x[(size_t)ROWS*DD];   // post-aggregation activations
__device__ float g_y[(size_t)ROWS*DD];   // pre-aggregation (XW) results

// ---------------- 1) adjacency lists + deg^{-1/2} ---------------------------
// Ahat = (conn!=0) + I  (diagonal can be 2 if conn[i][i]!=0).
// deg[j] = column sum of Ahat = row nnz + 1 (conn is symmetric).
// Neighbor list for row i = all j with conn[i][j]!=0, plus i appended once
// (so a set diagonal contributes weight 2 via the duplicate entry).
__global__ void build_adj(const int* __restrict__ conn) {
    int warp = (blockIdx.x * blockDim.x + threadIdx.x) >> 5;
    int lane = threadIdx.x & 31;
    if (warp >= ROWS) return;
    int i = warp & (NN - 1);
    size_t base = (size_t)warp * NN;
    int cnt = 0;
    #pragma unroll
    for (int t = 0; t < NN / 32; t++) {
        int j = lane + t * 32;
        int v = (conn[base + j] != 0);
        unsigned m = __ballot_sync(0xffffffffu, v);
        if (v) {
            int pos = cnt + __popc(m & ((1u << lane) - 1u));
            if (pos < MAXD - 1) g_nbr[(size_t)warp * MAXD + pos] = j;
        }
        cnt += __popc(m);
    }
    if (lane == 0) {
        int c = cnt < (MAXD - 1) ? cnt : (MAXD - 1);
        g_nbr[(size_t)warp * MAXD + c] = i;   // self loop (the +I)
        g_cnt[warp] = c + 1;
        g_dinv[warp] = rsqrtf((float)(cnt + 1));
    }
}

// ---------------- 2) tf32 WMMA GEMM: C(65536 x 128) = A @ W ----------------
// CONCAT=true : A row r = [node_feat[r, 0:92] | bond_feat[r, 0:512]], K = 604
// CONCAT=false: A = g_x, K = 128
// Always writes g_y. Block: 256 thr (8 warps), tile 128x128, warp 32x64,
// Kt = 32 staged in shared.
template<int KDIM, bool CONCAT>
__global__ void gemm_wmma(const float* __restrict__ A0,   // node (CONCAT) / unused
                          const float* __restrict__ A1,   // bond (CONCAT) / unused
                          const float* __restrict__ W) {
    constexpr int KT = 32;
    constexpr int NT = (KDIM + KT - 1) / KT;
    __shared__ float As[128][40];   // [m][k], ld 40 (pad for conflicts/alignment)
    __shared__ float Bs[32][128];   // [k][n]

    int tid  = threadIdx.x;
    int warp = tid >> 5;
    int wm   = warp & 3;            // 4 warp rows of 32
    int wn   = warp >> 2;           // 2 warp cols of 64
    int rowbase = blockIdx.x * 128;

    wmma::fragment<wmma::accumulator, 16, 16, 8, float> acc[2][4];
    #pragma unroll
    for (int a = 0; a < 2; a++)
        #pragma unroll
        for (int b = 0; b < 4; b++)
            wmma::fill_fragment(acc[a][b], 0.0f);

    for (int kt = 0; kt < NT; kt++) {
        int kbase = kt * KT;
        // stage A: 128x32
        #pragma unroll
        for (int q = 0; q < 16; q++) {
            int e = q * 256 + tid;
            int m = e >> 5, k = e & 31;
            int kg = kbase + k;
            float v;
            if (CONCAT) {
                int r = rowbase + m;
                if (kg < PF)       v = A0[(size_t)r * PF + kg];
                else if (kg < K0)  v = A1[(size_t)r * NN + (kg - PF)];
                else               v = 0.0f;
            } else {
                v = g_x[(size_t)(rowbase + m) * KDIM + kg];  // KDIM=128: kg always valid
            }
            As[m][k] = wmma::__float_to_tf32(v);
        }
        // stage B: 32x128
        #pragma unroll
        for (int q = 0; q < 16; q++) {
            int e = q * 256 + tid;
            int k = e >> 7, n = e & 127;
            int kg = kbase + k;
            float v = (kg < KDIM) ? W[(size_t)kg * DD + n] : 0.0f;
            Bs[k][n] = wmma::__float_to_tf32(v);
        }
        __syncthreads();
        #pragma unroll
        for (int kf = 0; kf < 4; kf++) {
            wmma::fragment<wmma::matrix_a, 16, 16, 8, wmma::precision::tf32, wmma::row_major> af[2];
            wmma::fragment<wmma::matrix_b, 16, 16, 8, wmma::precision::tf32, wmma::row_major> bf[4];
            #pragma unroll
            for (int a = 0; a < 2; a++)
                wmma::load_matrix_sync(af[a], &As[wm * 32 + a * 16][kf * 8], 40);
            #pragma unroll
            for (int b = 0; b < 4; b++)
                wmma::load_matrix_sync(bf[b], &Bs[kf * 8][wn * 64 + b * 16], 128);
            #pragma unroll
            for (int a = 0; a < 2; a++)
                #pragma unroll
                for (int b = 0; b < 4; b++)
                    wmma::mma_sync(acc[a][b], af[a], bf[b], acc[a][b]);
        }
        __syncthreads();
    }
    #pragma unroll
    for (int a = 0; a < 2; a++)
        #pragma unroll
        for (int b = 0; b < 4; b++) {
            float* p = g_y + (size_t)(rowbase + wm * 32 + a * 16) * DD + wn * 64 + b * 16;
            wmma::store_matrix_sync(p, acc[a][b], DD, wmma::mem_row_major);
        }
}

// ---------------- 3) sparse normalized aggregation + bias -------------------
// out[j,f] = dinv[j] * sum_{u in list(j)} dinv[list[u]] * y[list[u], f] + b[f]
// Block: (graph s, 16-feature slab). Y slab staged in shared.
#define FB 16
__global__ void aggregate(const float* __restrict__ bias) {
    __shared__ float ysh[NN][FB + 4];   // stride 20 floats breaks bank alignment
    __shared__ float dsh[NN];
    int s   = blockIdx.x;
    int f0  = blockIdx.y * FB;
    int tid = threadIdx.x;
    size_t sbase = (size_t)s * NN;

    #pragma unroll
    for (int q = 0; q < (NN * FB) / 256; q++) {   // 32 iters
        int e = q * 256 + tid;
        int r = e >> 4, f = e & 15;
        ysh[r][f] = g_y[(sbase + r) * DD + f0 + f];
    }
    dsh[tid]       = g_dinv[sbase + tid];
    dsh[tid + 256] = g_dinv[sbase + tid + 256];
    __syncthreads();

    float bloc[FB];
    #pragma unroll
    for (int f = 0; f < FB; f++) bloc[f] = bias[f0 + f];

    #pragma unroll
    for (int p = 0; p < 2; p++) {
        int r = tid + p * 256;
        int cnt = g_cnt[sbase + r];
        const int* nb = g_nbr + (sbase + r) * MAXD;
        float acc[FB];
        #pragma unroll
        for (int f = 0; f < FB; f++) acc[f] = 0.0f;
        for (int u = 0; u < cnt; u++) {
            int j = nb[u];
            float w = dsh[j];
            #pragma unroll
            for (int f = 0; f < FB; f++) acc[f] += w * ysh[j][f];
        }
        float di = dsh[r];
        float* out = g_x + (sbase + r) * DD + f0;
        #pragma unroll
        for (int f = 0; f < FB; f++) out[f] = di * acc[f] + bloc[f];
    }
}

// ---------------- 4) pool + softplus + MLP head ------------------------------
__global__ void head_kernel(const float* __restrict__ Wh, const float* __restrict__ bh,
                            const float* __restrict__ Wi, const float* __restrict__ bi,
                            const float* __restrict__ We, const float* __restrict__ be,
                            const float* __restrict__ Wlb, const float* __restrict__ blb,
                            const float* __restrict__ Wub, const float* __restrict__ bub,
                            float* __restrict__ out) {
    __shared__ float part[256];
    __shared__ float sp[DD];
    __shared__ float hsh[HID];
    int s = blockIdx.x, tid = threadIdx.x;
    int f = tid & (DD - 1);
    int half = tid >> 7;
    size_t base = (size_t)s * NN * DD;
    float acc = 0.0f;
    for (int i = half * 256; i < half * 256 + 256; i++)
        acc += g_x[base + (size_t)i * DD + f];
    part[tid] = acc;
    __syncthreads();
    if (tid < DD) {
        float v = part[tid] + part[tid + 128];
        sp[tid] = (v > 20.0f) ? v : log1pf(expf(v));
    }
    __syncthreads();
    {
        float a = bh[tid];
        #pragma unroll 4
        for (int k = 0; k < DD; k++) a += sp[k] * Wh[k * HID + tid];
        hsh[tid] = a;
    }
    __syncthreads();
    if (tid < 100) {
        float a = bi[tid];
        #pragma unroll 4
        for (int k = 0; k < HID; k++) a += hsh[k] * Wi[k * 100 + tid];
        out[s * 100 + tid] = a;
    } else if (tid < 103) {
        const float* Wv = (tid == 100) ? We : (tid == 101) ? Wlb : Wub;
        float bv = (tid == 100) ? be[0] : (tid == 101) ? blb[0] : bub[0];
        float a = bv;
        for (int k = 0; k < HID; k++) a += hsh[k] * Wv[k];
        out[SB * 100 + (tid - 100) * SB + s] = a;
    }
}

// ---------------- launch -----------------------------------------------------
extern "C" void kernel_launch(void* const* d_in, const int* in_sizes, int n_in,
                              void* d_out, int out_size) {
    const float* node = (const float*)d_in[0];
    const float* bond = (const float*)d_in[1];
    const int*   conn = (const int*)d_in[2];
    // d_in[3] = batchAssign (implicit; unused)
    const float* W0 = (const float*)d_in[4];
    const float* b0 = (const float*)d_in[5];
    const float* W1 = (const float*)d_in[6];
    const float* b1 = (const float*)d_in[7];
    const float* W2 = (const float*)d_in[8];
    const float* b2 = (const float*)d_in[9];
    const float* Wh = (const float*)d_in[10];
    const float* bh = (const float*)d_in[11];
    const float* Wi = (const float*)d_in[12];
    const float* bi = (const float*)d_in[13];
    const float* We = (const float*)d_in[14];
    const float* be = (const float*)d_in[15];
    const float* Wlb = (const float*)d_in[16];
    const float* blb = (const float*)d_in[17];
    const float* Wub = (const float*)d_in[18];
    const float* bub = (const float*)d_in[19];
    float* out = (float*)d_out;

    dim3 aggGrid(SB, DD / FB);

    build_adj<<<ROWS / 8, 256>>>(conn);

    gemm_wmma<K0, true><<<ROWS / 128, 256>>>(node, bond, W0);
    aggregate<<<aggGrid, 256>>>(b0);

    gemm_wmma<DD, false><<<ROWS / 128, 256>>>(nullptr, nullptr, W1);
    aggregate<<<aggGrid, 256>>>(b1);

    gemm_wmma<DD, false><<<ROWS / 128, 256>>>(nullptr, nullptr, W2);
    aggregate<<<aggGrid, 256>>>(b2);

    head_kernel<<<SB, 256>>>(Wh, bh, Wi, bi, We, be, Wlb, blb, Wub, bub, out);
}

// round 5
// speedup vs baseline: 2.2968x; 2.2968x over previous
#include <cuda_runtime.h>
#include <mma.h>
#include <math.h>

using namespace nvcuda;

#define SB   128      // batch (graphs)
#define NN   512      // nodes per graph
#define PF   92       // node feature dim
#define K0   604      // PF + NN
#define DD   128      // hidden dim of GCN layers
#define HID  256
#define MAXD 96
#define ROWS (SB*NN)  // 65536

// ---------------- scratch (static device globals; no allocations) -----------
__device__ float g_dinv[ROWS];
__device__ int   g_cnt[ROWS];
__device__ int   g_nbr[(size_t)ROWS*MAXD];
__device__ float g_x[(size_t)ROWS*DD];   // post-aggregation activations
__device__ float g_y[(size_t)ROWS*DD];   // pre-aggregation (XW) results

// ---------------- 1) adjacency lists + deg^{-1/2} ---------------------------
// Ahat = (conn!=0) + I (diag may be 2 -> self index appears twice in list).
__global__ void build_adj(const int* __restrict__ conn) {
    int warp = (blockIdx.x * blockDim.x + threadIdx.x) >> 5;
    int lane = threadIdx.x & 31;
    if (warp >= ROWS) return;
    int i = warp & (NN - 1);
    size_t base = (size_t)warp * NN;
    int cnt = 0;
    #pragma unroll
    for (int t = 0; t < NN / 32; t++) {
        int j = lane + t * 32;
        int v = (conn[base + j] != 0);
        unsigned m = __ballot_sync(0xffffffffu, v);
        if (v) {
            int pos = cnt + __popc(m & ((1u << lane) - 1u));
            if (pos < MAXD - 1) g_nbr[(size_t)warp * MAXD + pos] = j;
        }
        cnt += __popc(m);
    }
    if (lane == 0) {
        int c = cnt < (MAXD - 1) ? cnt : (MAXD - 1);
        g_nbr[(size_t)warp * MAXD + c] = i;   // self loop (the +I)
        g_cnt[warp] = c + 1;
        g_dinv[warp] = rsqrtf((float)(cnt + 1));
    }
}

// ---------------- 2) tf32 WMMA GEMM: g_y(65536 x 128) = A @ W ---------------
// 512 threads, block tile 256x128, warp tile 64x32, K-tile 16,
// register-prefetch software pipeline (overlap LDG with MMA).
template<int KDIM, bool CONCAT>
__global__ void __launch_bounds__(512, 1)
gemm_wmma(const float* __restrict__ A0,   // node (CONCAT) / unused
          const float* __restrict__ A1,   // bond (CONCAT) / unused
          const float* __restrict__ W) {
    constexpr int KT = 16;
    constexpr int NT = (KDIM + KT - 1) / KT;
    __shared__ float As[256][20];    // [m][k], pad 20
    __shared__ float Bs[16][132];    // [k][n], pad 132

    int tid  = threadIdx.x;
    int warp = tid >> 5;
    int wm   = warp & 3;            // 4 warp rows of 64
    int wn   = warp >> 2;           // 4 warp cols of 32
    int rowbase = blockIdx.x * 256;

    wmma::fragment<wmma::accumulator, 16, 16, 8, float> acc[4][2];
    #pragma unroll
    for (int a = 0; a < 4; a++)
        #pragma unroll
        for (int b = 0; b < 2; b++)
            wmma::fill_fragment(acc[a][b], 0.0f);

    float areg[8], breg[4];

    // ---- staging helpers ----
    auto load_tiles = [&](int kt) {
        int kbase = kt * KT;
        #pragma unroll
        for (int q = 0; q < 8; q++) {
            int e = q * 512 + tid;
            int m = e >> 4, k = e & 15;
            int kg = kbase + k;
            float v;
            if (CONCAT) {
                int r = rowbase + m;
                if (kg < PF)       v = A0[(size_t)r * PF + kg];
                else if (kg < K0)  v = A1[(size_t)r * NN + (kg - PF)];
                else               v = 0.0f;
            } else {
                v = g_x[(size_t)(rowbase + m) * DD + kg];
            }
            areg[q] = v;
        }
        #pragma unroll
        for (int q = 0; q < 4; q++) {
            int e = q * 512 + tid;
            int k = e >> 7, n = e & 127;
            int kg = kbase + k;
            breg[q] = (kg < KDIM) ? W[(size_t)kg * DD + n] : 0.0f;
        }
    };
    auto sts_tiles = [&]() {
        #pragma unroll
        for (int q = 0; q < 8; q++) {
            int e = q * 512 + tid;
            As[e >> 4][e & 15] = wmma::__float_to_tf32(areg[q]);
        }
        #pragma unroll
        for (int q = 0; q < 4; q++) {
            int e = q * 512 + tid;
            Bs[e >> 7][e & 127] = wmma::__float_to_tf32(breg[q]);
        }
    };

    load_tiles(0);
    sts_tiles();
    __syncthreads();

    for (int kt = 0; kt < NT; kt++) {
        if (kt + 1 < NT) load_tiles(kt + 1);   // LDG overlaps MMA below
        #pragma unroll
        for (int kf = 0; kf < 2; kf++) {
            wmma::fragment<wmma::matrix_a, 16, 16, 8, wmma::precision::tf32, wmma::row_major> af[4];
            wmma::fragment<wmma::matrix_b, 16, 16, 8, wmma::precision::tf32, wmma::row_major> bf[2];
            #pragma unroll
            for (int a = 0; a < 4; a++)
                wmma::load_matrix_sync(af[a], &As[wm * 64 + a * 16][kf * 8], 20);
            #pragma unroll
            for (int b = 0; b < 2; b++)
                wmma::load_matrix_sync(bf[b], &Bs[kf * 8][wn * 32 + b * 16], 132);
            #pragma unroll
            for (int a = 0; a < 4; a++)
                #pragma unroll
                for (int b = 0; b < 2; b++)
                    wmma::mma_sync(acc[a][b], af[a], bf[b], acc[a][b]);
        }
        __syncthreads();
        if (kt + 1 < NT) {
            sts_tiles();
            __syncthreads();
        }
    }

    #pragma unroll
    for (int a = 0; a < 4; a++)
        #pragma unroll
        for (int b = 0; b < 2; b++) {
            float* p = g_y + (size_t)(rowbase + wm * 64 + a * 16) * DD + wn * 32 + b * 16;
            wmma::store_matrix_sync(p, acc[a][b], DD, wmma::mem_row_major);
        }
}

// ---------------- 3) sparse normalized aggregation + bias -------------------
// Block = (graph s, 64-feature half). Stage ysh[j] = dinv[j]*y[j] (pre-scaled).
// Warp = row; lanes = features (conflict-free LDS.64). Neighbor idx loaded
// coalesced 32-at-a-time, broadcast via shfl.
__global__ void __launch_bounds__(512, 1)
aggregate(const float* __restrict__ bias) {
    extern __shared__ float ysh[];   // NN * 64 floats = 128KB
    int s   = blockIdx.x;
    int f0  = blockIdx.y * 64;
    int tid = threadIdx.x;
    int lane = tid & 31, warp = tid >> 5;
    size_t sbase = (size_t)s * NN;

    // stage + pre-scale by source dinv
    #pragma unroll
    for (int q = 0; q < 16; q++) {
        int e = q * 512 + tid;
        int r = e >> 4, c = e & 15;
        float4 v = *(const float4*)&g_y[((sbase + r) << 7) + f0 + (c << 2)];
        float d = g_dinv[sbase + r];
        v.x *= d; v.y *= d; v.z *= d; v.w *= d;
        *(float4*)&ysh[(r << 6) + (c << 2)] = v;
    }
    __syncthreads();

    float2 bl = *(const float2*)&bias[f0 + lane * 2];

    for (int r = warp; r < NN; r += 16) {
        int cnt = g_cnt[sbase + r];
        const int* nb = g_nbr + (size_t)(sbase + r) * MAXD;
        float accx = 0.0f, accy = 0.0f;
        for (int base = 0; base < cnt; base += 32) {
            int my = base + lane;
            int idx = (my < cnt) ? nb[my] : 0;
            int lim = min(32, cnt - base);
            #pragma unroll 4
            for (int k = 0; k < lim; k++) {
                int j = __shfl_sync(0xffffffffu, idx, k);
                float2 v = *(const float2*)&ysh[(j << 6) + lane * 2];
                accx += v.x; accy += v.y;
            }
        }
        float di = g_dinv[sbase + r];
        float2 o;
        o.x = di * accx + bl.x;
        o.y = di * accy + bl.y;
        *(float2*)&g_x[((sbase + r) << 7) + f0 + lane * 2] = o;
    }
}

// ---------------- 4) pool + softplus + MLP head ------------------------------
__global__ void head_kernel(const float* __restrict__ Wh, const float* __restrict__ bh,
                            const float* __restrict__ Wi, const float* __restrict__ bi,
                            const float* __restrict__ We, const float* __restrict__ be,
                            const float* __restrict__ Wlb, const float* __restrict__ blb,
                            const float* __restrict__ Wub, const float* __restrict__ bub,
                            float* __restrict__ out) {
    __shared__ float part[256];
    __shared__ float sp[DD];
    __shared__ float hsh[HID];
    int s = blockIdx.x, tid = threadIdx.x;
    int f = tid & (DD - 1);
    int half = tid >> 7;
    size_t base = (size_t)s * NN * DD;
    float acc = 0.0f;
    for (int i = half * 256; i < half * 256 + 256; i++)
        acc += g_x[base + (size_t)i * DD + f];
    part[tid] = acc;
    __syncthreads();
    if (tid < DD) {
        float v = part[tid] + part[tid + 128];
        sp[tid] = (v > 20.0f) ? v : log1pf(expf(v));
    }
    __syncthreads();
    {
        float a = bh[tid];
        #pragma unroll 4
        for (int k = 0; k < DD; k++) a += sp[k] * Wh[k * HID + tid];
        hsh[tid] = a;
    }
    __syncthreads();
    if (tid < 100) {
        float a = bi[tid];
        #pragma unroll 4
        for (int k = 0; k < HID; k++) a += hsh[k] * Wi[k * 100 + tid];
        out[s * 100 + tid] = a;
    } else if (tid < 103) {
        const float* Wv = (tid == 100) ? We : (tid == 101) ? Wlb : Wub;
        float bv = (tid == 100) ? be[0] : (tid == 101) ? blb[0] : bub[0];
        float a = bv;
        for (int k = 0; k < HID; k++) a += hsh[k] * Wv[k];
        out[SB * 100 + (tid - 100) * SB + s] = a;
    }
}

// ---------------- launch -----------------------------------------------------
extern "C" void kernel_launch(void* const* d_in, const int* in_sizes, int n_in,
                              void* d_out, int out_size) {
    const float* node = (const float*)d_in[0];
    const float* bond = (const float*)d_in[1];
    const int*   conn = (const int*)d_in[2];
    // d_in[3] = batchAssign (implicit; unused)
    const float* W0 = (const float*)d_in[4];
    const float* b0 = (const float*)d_in[5];
    const float* W1 = (const float*)d_in[6];
    const float* b1 = (const float*)d_in[7];
    const float* W2 = (const float*)d_in[8];
    const float* b2 = (const float*)d_in[9];
    const float* Wh = (const float*)d_in[10];
    const float* bh = (const float*)d_in[11];
    const float* Wi = (const float*)d_in[12];
    const float* bi = (const float*)d_in[13];
    const float* We = (const float*)d_in[14];
    const float* be = (const float*)d_in[15];
    const float* Wlb = (const float*)d_in[16];
    const float* blb = (const float*)d_in[17];
    const float* Wub = (const float*)d_in[18];
    const float* bub = (const float*)d_in[19];
    float* out = (float*)d_out;

    // One-time idempotent configuration (host-side, not a stream op; kept out
    // of the replayed work for cleanliness).
    static bool configured = false;
    if (!configured) {
        cudaFuncSetAttribute(aggregate, cudaFuncAttributeMaxDynamicSharedMemorySize, 131072);
        configured = true;
    }

    dim3 aggGrid(SB, 2);

    build_adj<<<ROWS / 8, 256>>>(conn);

    gemm_wmma<K0, true><<<ROWS / 256, 512>>>(node, bond, W0);
    aggregate<<<aggGrid, 512, 131072>>>(b0);

    gemm_wmma<DD, false><<<ROWS / 256, 512>>>(nullptr, nullptr, W1);
    aggregate<<<aggGrid, 512, 131072>>>(b1);

    gemm_wmma<DD, false><<<ROWS / 256, 512>>>(nullptr, nullptr, W2);
    aggregate<<<aggGrid, 512, 131072>>>(b2);

    head_kernel<<<SB, 256>>>(Wh, bh, Wi, bi, We, be, Wlb, blb, Wub, bub, out);
}

// round 11
// speedup vs baseline: 2.4917x; 1.0849x over previous
#include <cuda_runtime.h>
#include <cstdint>
#include <mma.h>
#include <math.h>

using namespace nvcuda;

#define SB   128      // batch (graphs)
#define NN   512      // nodes per graph
#define PF   92       // node feature dim
#define K0   604      // PF + NN
#define DD   128      // hidden dim of GCN layers
#define HID  256
#define MAXD 96
#define ROWS (SB*NN)  // 65536

// ---------------- scratch (static device globals; no allocations) -----------
__device__ float g_dinv[ROWS];
__device__ int   g_cnt[ROWS];
__device__ int   g_nbr[(size_t)ROWS*MAXD];
__device__ float g_x[(size_t)ROWS*DD];   // post-aggregation activations
__device__ float g_y[(size_t)ROWS*DD];   // pre-aggregation (XW) results
__device__ __align__(16) float g_zero4[4];   // zero-filled quad for OOB cp.async

// ---------------- cp.async helpers ------------------------------------------
__device__ __forceinline__ void cp16(void* smem_dst, const void* gmem_src) {
    unsigned int s = (unsigned int)__cvta_generic_to_shared(smem_dst);
    asm volatile("cp.async.cg.shared.global [%0], [%1], 16;\n" :: "r"(s), "l"(gmem_src));
}
__device__ __forceinline__ void cp_commit() {
    asm volatile("cp.async.commit_group;\n" ::: "memory");
}
__device__ __forceinline__ void cp_wait1() {
    asm volatile("cp.async.wait_group 1;\n" ::: "memory");
}

// ---------------- 1) adjacency lists + deg^{-1/2} ---------------------------
// Ahat = (conn!=0) + I (diag may be 2 -> self index appears twice in list).
__global__ void build_adj(const int* __restrict__ conn) {
    int warp = (blockIdx.x * blockDim.x + threadIdx.x) >> 5;
    int lane = threadIdx.x & 31;
    if (warp >= ROWS) return;
    int i = warp & (NN - 1);
    size_t base = (size_t)warp * NN;
    int cnt = 0;
    #pragma unroll
    for (int t = 0; t < NN / 32; t++) {
        int j = lane + t * 32;
        int v = (conn[base + j] != 0);
        unsigned m = __ballot_sync(0xffffffffu, v);
        if (v) {
            int pos = cnt + __popc(m & ((1u << lane) - 1u));
            if (pos < MAXD - 1) g_nbr[(size_t)warp * MAXD + pos] = j;
        }
        cnt += __popc(m);
    }
    if (lane == 0) {
        int c = cnt < (MAXD - 1) ? cnt : (MAXD - 1);
        g_nbr[(size_t)warp * MAXD + c] = i;   // self loop (the +I)
        g_cnt[warp] = c + 1;
        g_dinv[warp] = rsqrtf((float)(cnt + 1));
    }
}

// ---------------- 2) tf32 WMMA GEMM, cp.async 3-stage pipeline --------------
// g_y(65536 x 128) = A @ W.  Block: 256 thr, tile 128x128, warp 64x32, KT=32.
// fp32 staged raw via cp.async; RN tf32 rounding applied IN REGISTERS on the
// loaded fragments (cvt.rna.tf32) to avoid HW-truncation bias.
#define KT      32
#define A_LD    36
#define B_LD    132
#define A_STG   (128 * A_LD)       // floats per A stage
#define B_STG   (KT * B_LD)        // floats per B stage
#define GEMM_SMEM_BYTES ((3 * (A_STG + B_STG)) * 4)   // 105984

template<class Frag>
__device__ __forceinline__ void round_tf32(Frag& f) {
    #pragma unroll
    for (int i = 0; i < f.num_elements; i++)
        f.x[i] = wmma::__float_to_tf32(f.x[i]);
}

template<int KDIM, bool CONCAT>
__global__ void __launch_bounds__(256, 2)
gemm_wmma(const float* __restrict__ A0,   // node (CONCAT) / unused
          const float* __restrict__ A1,   // bond (CONCAT) / unused
          const float* __restrict__ W) {
    constexpr int NT = (KDIM + KT - 1) / KT;
    extern __shared__ float smem[];
    float* Abase = smem;                  // 3 stages of A
    float* Bbase = smem + 3 * A_STG;      // 3 stages of B

    int tid  = threadIdx.x;
    int warp = tid >> 5;
    int wm   = warp & 1;            // 2 warp rows of 64
    int wn   = warp >> 1;           // 4 warp cols of 32
    int rowbase = blockIdx.x * 128;

    wmma::fragment<wmma::accumulator, 16, 16, 8, float> acc[4][2];
    #pragma unroll
    for (int a = 0; a < 4; a++)
        #pragma unroll
        for (int b = 0; b < 2; b++)
            wmma::fill_fragment(acc[a][b], 0.0f);

    auto stage_load = [&](int kt, int st) {
        int kbase = kt * KT;
        float* As = Abase + st * A_STG;
        float* Bs = Bbase + st * B_STG;
        // A tile: 128 rows x 32 cols = 1024 16B chunks, 4 per thread
        #pragma unroll
        for (int q = 0; q < 4; q++) {
            int c  = q * 256 + tid;
            int m  = c >> 3;
            int k4 = (c & 7) << 2;
            int kg = kbase + k4;
            const float* src;
            if (CONCAT) {
                int r = rowbase + m;
                if (kg < PF)      src = A0 + (size_t)r * PF + kg;
                else if (kg < K0) src = A1 + (size_t)r * NN + (kg - PF);
                else              src = g_zero4;
            } else {
                src = g_x + (((size_t)(rowbase + m)) << 7) + kg;   // KDIM=128
            }
            cp16(&As[m * A_LD + k4], src);
        }
        // B tile: 32 rows x 128 cols = 1024 chunks, 4 per thread
        #pragma unroll
        for (int q = 0; q < 4; q++) {
            int c  = q * 256 + tid;
            int k  = c >> 5;
            int n4 = (c & 31) << 2;
            int kg = kbase + k;
            const float* src = (kg < KDIM) ? (W + (size_t)kg * DD + n4)
                                           : (const float*)g_zero4;
            cp16(&Bs[k * B_LD + n4], src);
        }
    };

    stage_load(0, 0); cp_commit();
    stage_load(1, 1); cp_commit();

    for (int kt = 0; kt < NT; kt++) {
        int buf = kt % 3;
        cp_wait1();            // tile kt resident (always-commit keeps count exact)
        __syncthreads();       // also guards buf (kt+2)%3 == (kt-1)%3 reuse below
        if (kt + 2 < NT) stage_load(kt + 2, (kt + 2) % 3);
        cp_commit();           // empty group in the tail keeps wait_group math valid
        const float* As = Abase + buf * A_STG;
        const float* Bs = Bbase + buf * B_STG;
        #pragma unroll
        for (int kf = 0; kf < 4; kf++) {
            wmma::fragment<wmma::matrix_a, 16, 16, 8, wmma::precision::tf32, wmma::row_major> af[4];
            wmma::fragment<wmma::matrix_b, 16, 16, 8, wmma::precision::tf32, wmma::row_major> bf[2];
            #pragma unroll
            for (int a = 0; a < 4; a++) {
                wmma::load_matrix_sync(af[a], As + (wm * 64 + a * 16) * A_LD + kf * 8, A_LD);
                round_tf32(af[a]);   // RN tf32 (cvt.rna) — kills truncation bias
            }
            #pragma unroll
            for (int b = 0; b < 2; b++) {
                wmma::load_matrix_sync(bf[b], Bs + (kf * 8) * B_LD + wn * 32 + b * 16, B_LD);
                round_tf32(bf[b]);
            }
            #pragma unroll
            for (int a = 0; a < 4; a++)
                #pragma unroll
                for (int b = 0; b < 2; b++)
                    wmma::mma_sync(acc[a][b], af[a], bf[b], acc[a][b]);
        }
    }

    #pragma unroll
    for (int a = 0; a < 4; a++)
        #pragma unroll
        for (int b = 0; b < 2; b++) {
            float* p = g_y + (size_t)(rowbase + wm * 64 + a * 16) * DD + wn * 32 + b * 16;
            wmma::store_matrix_sync(p, acc[a][b], DD, wmma::mem_row_major);
        }
}

// ---------------- 3) sparse normalized aggregation + bias -------------------
// Block = (graph s, 64-feature half). Stage ysh[j] = dinv[j]*y[j] (pre-scaled).
// Warp = row; lanes = features (conflict-free LDS.64).
__global__ void __launch_bounds__(512, 1)
aggregate(const float* __restrict__ bias) {
    extern __shared__ float ysh[];   // NN * 64 floats = 128KB
    int s   = blockIdx.x;
    int f0  = blockIdx.y * 64;
    int tid = threadIdx.x;
    int lane = tid & 31, warp = tid >> 5;
    size_t sbase = (size_t)s * NN;

    #pragma unroll
    for (int q = 0; q < 16; q++) {
        int e = q * 512 + tid;
        int r = e >> 4, c = e & 15;
        float4 v = *(const float4*)&g_y[((sbase + r) << 7) + f0 + (c << 2)];
        float d = g_dinv[sbase + r];
        v.x *= d; v.y *= d; v.z *= d; v.w *= d;
        *(float4*)&ysh[(r << 6) + (c << 2)] = v;
    }
    __syncthreads();

    float2 bl = *(const float2*)&bias[f0 + lane * 2];

    for (int r = warp; r < NN; r += 16) {
        int cnt = g_cnt[sbase + r];
        const int* nb = g_nbr + (size_t)(sbase + r) * MAXD;
        float accx = 0.0f, accy = 0.0f;
        for (int base = 0; base < cnt; base += 32) {
            int my = base + lane;
            int idx = (my < cnt) ? nb[my] : 0;
            int lim = min(32, cnt - base);
            #pragma unroll 4
            for (int k = 0; k < lim; k++) {
                int j = __shfl_sync(0xffffffffu, idx, k);
                float2 v = *(const float2*)&ysh[(j << 6) + lane * 2];
                accx += v.x; accy += v.y;
            }
        }
        float di = g_dinv[sbase + r];
        float2 o;
        o.x = di * accx + bl.x;
        o.y = di * accy + bl.y;
        *(float2*)&g_x[((sbase + r) << 7) + f0 + lane * 2] = o;
    }
}

// ---------------- 4) pool + softplus + MLP head ------------------------------
__global__ void head_kernel(const float* __restrict__ Wh, const float* __restrict__ bh,
                            const float* __restrict__ Wi, const float* __restrict__ bi,
                            const float* __restrict__ We, const float* __restrict__ be,
                            const float* __restrict__ Wlb, const float* __restrict__ blb,
                            const float* __restrict__ Wub, const float* __restrict__ bub,
                            float* __restrict__ out) {
    __shared__ float part[256];
    __shared__ float sp[DD];
    __shared__ float hsh[HID];
    int s = blockIdx.x, tid = threadIdx.x;
    int f = tid & (DD - 1);
    int half = tid >> 7;
    size_t base = (size_t)s * NN * DD;
    float acc = 0.0f;
    for (int i = half * 256; i < half * 256 + 256; i++)
        acc += g_x[base + (size_t)i * DD + f];
    part[tid] = acc;
    __syncthreads();
    if (tid < DD) {
        float v = part[tid] + part[tid + 128];
        sp[tid] = (v > 20.0f) ? v : log1pf(expf(v));
    }
    __syncthreads();
    {
        float a = bh[tid];
        #pragma unroll 4
        for (int k = 0; k < DD; k++) a += sp[k] * Wh[k * HID + tid];
        hsh[tid] = a;
    }
    __syncthreads();
    if (tid < 100) {
        float a = bi[tid];
        #pragma unroll 4
        for (int k = 0; k < HID; k++) a += hsh[k] * Wi[k * 100 + tid];
        out[s * 100 + tid] = a;
    } else if (tid < 103) {
        const float* Wv = (tid == 100) ? We : (tid == 101) ? Wlb : Wub;
        float bv = (tid == 100) ? be[0] : (tid == 101) ? blb[0] : bub[0];
        float a = bv;
        for (int k = 0; k < HID; k++) a += hsh[k] * Wv[k];
        out[SB * 100 + (tid - 100) * SB + s] = a;
    }
}

// ---------------- launch -----------------------------------------------------
extern "C" void kernel_launch(void* const* d_in, const int* in_sizes, int n_in,
                              void* d_out, int out_size) {
    const float* node = (const float*)d_in[0];
    const float* bond = (const float*)d_in[1];
    const int*   conn = (const int*)d_in[2];
    // d_in[3] = batchAssign (implicit; unused)
    const float* W0 = (const float*)d_in[4];
    const float* b0 = (const float*)d_in[5];
    const float* W1 = (const float*)d_in[6];
    const float* b1 = (const float*)d_in[7];
    const float* W2 = (const float*)d_in[8];
    const float* b2 = (const float*)d_in[9];
    const float* Wh = (const float*)d_in[10];
    const float* bh = (const float*)d_in[11];
    const float* Wi = (const float*)d_in[12];
    const float* bi = (const float*)d_in[13];
    const float* We = (const float*)d_in[14];
    const float* be = (const float*)d_in[15];
    const float* Wlb = (const float*)d_in[16];
    const float* blb = (const float*)d_in[17];
    const float* Wub = (const float*)d_in[18];
    const float* bub = (const float*)d_in[19];
    float* out = (float*)d_out;

    // One-time idempotent configuration (host-side, not a stream op).
    static bool configured = false;
    if (!configured) {
        cudaFuncSetAttribute(aggregate, cudaFuncAttributeMaxDynamicSharedMemorySize, 131072);
        cudaFuncSetAttribute(gemm_wmma<K0, true>,
                             cudaFuncAttributeMaxDynamicSharedMemorySize, GEMM_SMEM_BYTES);
        cudaFuncSetAttribute(gemm_wmma<DD, false>,
                             cudaFuncAttributeMaxDynamicSharedMemorySize, GEMM_SMEM_BYTES);
        configured = true;
    }

    dim3 aggGrid(SB, 2);

    build_adj<<<ROWS / 8, 256>>>(conn);

    gemm_wmma<K0, true><<<ROWS / 128, 256, GEMM_SMEM_BYTES>>>(node, bond, W0);
    aggregate<<<aggGrid, 512, 131072>>>(b0);

    gemm_wmma<DD, false><<<ROWS / 128, 256, GEMM_SMEM_BYTES>>>(nullptr, nullptr, W1);
    aggregate<<<aggGrid, 512, 131072>>>(b1);

    gemm_wmma<DD, false><<<ROWS / 128, 256, GEMM_SMEM_BYTES>>>(nullptr, nullptr, W2);
    aggregate<<<aggGrid, 512, 131072>>>(b2);

    head_kernel<<<SB, 256>>>(Wh, bh, Wi, bi, We, be, Wlb, blb, Wub, bub, out);
}